// round 2
// baseline (speedup 1.0000x reference)
#include <cuda_runtime.h>
#include <cuda_bf16.h>
#include <math.h>

// ---------------- problem constants ----------------
#define Bn 2
#define Tn 4096
#define Dn 1024
#define Hn 16
#define KDn 512
#define VDn 1024
#define HKn 32
#define HVn 64
#define CHUNKn 64
#define NC (Tn / CHUNKn)          // 64 chunks
#define NTOK (Bn * Tn)            // 8192 tokens
#define BH (Bn * Hn)              // 32
#define NCB (NC * BH)             // 2048 chunk-heads
#define SCALE_Q 0.17677669529663687f  // 1/sqrt(32)

// ---------------- scratch (static device globals; no allocation) ----------------
__device__ float d_Q[NTOK * KDn];        // 16 MB
__device__ float d_Kb[NTOK * KDn];       // 16 MB
__device__ float d_Vb[NTOK * VDn];       // 32 MB
__device__ float d_Gb[NTOK * VDn];       // 32 MB
__device__ float d_GK[NTOK * KDn];       // 16 MB   (gate log-decay values)
__device__ float d_t16[NTOK * 16];       // 0.5 MB
__device__ float d_M[NCB * HKn * HVn];   // 16 MB   per-chunk state contribution
__device__ float d_Sb[NCB * HKn * HVn];  // 16 MB   state BEFORE each chunk
__device__ float d_dl[NCB * HKn];        // 0.25 MB chunk decay exp(b_last)
__device__ float d_O[NTOK * VDn];        // 32 MB   o (then gated/normed, input to Wo)

// ---------------- generic SGEMM: C[M,N] = A[M,K] @ B[K,N], row-major ----------------
// 128x128 tile, BK=16, 256 threads, 8x8 per-thread microtile.
__global__ __launch_bounds__(256) void sgemm128(
    const float* __restrict__ A, const float* __restrict__ B,
    float* __restrict__ C, int M, int N, int K)
{
    __shared__ float As[16][128];
    __shared__ float Bs[16][128];
    const int tid = threadIdx.x;
    const int bm = blockIdx.y * 128;
    const int bn = blockIdx.x * 128;
    const int tx = tid & 15;         // N-dir
    const int ty = tid >> 4;         // M-dir

    const int arow = tid >> 2;           // 0..63
    const int acol = (tid & 3) * 4;      // 0,4,8,12
    const int brow = tid >> 5;           // 0..7
    const int bcol = (tid & 31) * 4;     // 0..124

    float acc[8][8];
    #pragma unroll
    for (int i = 0; i < 8; i++)
        #pragma unroll
        for (int j = 0; j < 8; j++) acc[i][j] = 0.f;

    for (int k0 = 0; k0 < K; k0 += 16) {
        #pragma unroll
        for (int r = 0; r < 2; r++) {
            int row = arow + r * 64;
            float4 a = *(const float4*)&A[(size_t)(bm + row) * K + k0 + acol];
            As[acol + 0][row] = a.x;
            As[acol + 1][row] = a.y;
            As[acol + 2][row] = a.z;
            As[acol + 3][row] = a.w;
        }
        #pragma unroll
        for (int r = 0; r < 2; r++) {
            int row = brow + r * 8;
            *(float4*)&Bs[row][bcol] = *(const float4*)&B[(size_t)(k0 + row) * N + bn + bcol];
        }
        __syncthreads();
        #pragma unroll
        for (int kk = 0; kk < 16; kk++) {
            float ra[8], rb[8];
            *(float4*)&ra[0] = *(float4*)&As[kk][ty * 8];
            *(float4*)&ra[4] = *(float4*)&As[kk][ty * 8 + 4];
            *(float4*)&rb[0] = *(float4*)&Bs[kk][tx * 8];
            *(float4*)&rb[4] = *(float4*)&Bs[kk][tx * 8 + 4];
            #pragma unroll
            for (int i = 0; i < 8; i++)
                #pragma unroll
                for (int j = 0; j < 8; j++)
                    acc[i][j] += ra[i] * rb[j];
        }
        __syncthreads();
    }
    #pragma unroll
    for (int i = 0; i < 8; i++) {
        size_t row = (size_t)(bm + ty * 8 + i);
        #pragma unroll
        for (int j = 0; j < 8; j += 4) {
            float4 v = make_float4(acc[i][j], acc[i][j+1], acc[i][j+2], acc[i][j+3]);
            *(float4*)&C[row * N + bn + tx * 8 + j] = v;
        }
    }
}

// ---------------- gk low-rank stage 1: t16 = x @ Wgk1  (8192 x 16, K=1024) ----------
__global__ __launch_bounds__(256) void gemm_gk1(const float* __restrict__ X,
                                                const float* __restrict__ W)
{
    __shared__ float red[256];
    const int m = blockIdx.x;
    const int tx = threadIdx.x & 15;   // n
    const int ty = threadIdx.x >> 4;   // k-split
    float acc = 0.f;
    const float* xr = X + (size_t)m * Dn;
    for (int k = ty; k < Dn; k += 16)
        acc += xr[k] * W[k * 16 + tx];
    red[threadIdx.x] = acc;
    __syncthreads();
    for (int s = 8; s > 0; s >>= 1) {
        if (ty < s) red[ty * 16 + tx] += red[(ty + s) * 16 + tx];
        __syncthreads();
    }
    if (ty == 0) d_t16[m * 16 + tx] = red[tx];
}

// ---------------- gk stage 2: GK = log_sigmoid(t16 @ Wgk2 + bgk) / 16 ---------------
__global__ __launch_bounds__(256) void gk_kernel(const float* __restrict__ W2,
                                                 const float* __restrict__ bgk)
{
    int idx = blockIdx.x * blockDim.x + threadIdx.x;  // NTOK*KDn
    int m = idx >> 9;
    int n = idx & 511;
    const float* t = d_t16 + m * 16;
    float z = bgk[n];
    #pragma unroll
    for (int k = 0; k < 16; k++) z += t[k] * W2[k * KDn + n];
    // stable log-sigmoid
    float ls = fminf(z, 0.f) - log1pf(expf(-fabsf(z)));
    d_GK[idx] = ls * (1.f / 16.f);
}

// ---------------- attention phase A: per chunk-head local work ----------------------
// Computes: M_c = (k*exp(b_last-b))^T @ v, dl_c = exp(b_last), o_intra = tril(qe@kd^T)@v
__global__ __launch_bounds__(256) void attn_chunk_kernel()
{
    __shared__ float s_qe[2048];   // gc -> b -> qe (in-place)
    __shared__ float s_kd[2048];   // k * exp(-b), XOR-swizzled
    __shared__ float s_v[4096];
    __shared__ float s_A[2048];    // one 32-row half of A
    __shared__ float s_bl[32], s_dl[32];

    const int cb = blockIdx.x;            // c*32 + bh
    const int bh = cb & 31, c = cb >> 5;
    const int b = bh >> 4, h = bh & 15;
    const int t = threadIdx.x;
    const size_t tok0 = (size_t)b * Tn + (size_t)c * CHUNKn;

    for (int e = t; e < 2048; e += 256) {
        int i = e >> 5, k = e & 31;
        s_qe[e] = d_GK[(tok0 + i) * KDn + h * HKn + k];
    }
    __syncthreads();
    if (t < 32) {   // inclusive cumsum over the 64 chunk positions, per k-dim
        float run = 0.f;
        for (int i = 0; i < 64; i++) { run += s_qe[i * 32 + t]; s_qe[i * 32 + t] = run; }
        s_bl[t] = run;
        s_dl[t] = expf(run);
    }
    __syncthreads();
    for (int e = t; e < 2048; e += 256) {
        int i = e >> 5, k = e & 31;
        float bb = s_qe[e];
        float kv = d_Kb[(tok0 + i) * KDn + h * HKn + k];
        s_kd[i * 32 + ((k ^ i) & 31)] = kv * expf(-bb);
        float qv = d_Q[(tok0 + i) * KDn + h * HKn + k];
        s_qe[e] = qv * expf(bb) * SCALE_Q;
    }
    for (int e = t; e < 4096; e += 256) {
        int i = e >> 6, v = e & 63;
        s_v[e] = d_Vb[(tok0 + i) * VDn + h * HVn + v];
    }
    __syncthreads();
    // M[k][v] = exp(bl[k]) * sum_j kd[j][k] * v[j][v]
    for (int o = t; o < 2048; o += 256) {
        int k = o >> 6, v = o & 63;
        float acc = 0.f;
        #pragma unroll 8
        for (int j = 0; j < 64; j++)
            acc += s_kd[j * 32 + ((k ^ j) & 31)] * s_v[j * 64 + v];
        d_M[(size_t)cb * 2048 + o] = acc * s_dl[k];
    }
    if (t < 32) d_dl[cb * 32 + t] = s_dl[t];

    // intra-chunk output, 32-row halves of A
    #pragma unroll
    for (int half = 0; half < 2; half++) {
        __syncthreads();
        for (int o = t; o < 2048; o += 256) {
            int il = o >> 6, j = o & 63;
            int i = half * 32 + il;
            float acc = 0.f;
            if (j <= i) {
                #pragma unroll
                for (int k = 0; k < 32; k++)
                    acc += s_qe[i * 32 + k] * s_kd[j * 32 + ((k ^ j) & 31)];
            }
            s_A[o] = acc;
        }
        __syncthreads();
        for (int o = t; o < 2048; o += 256) {
            int il = o >> 6, v = o & 63;
            int i = half * 32 + il;
            float acc = 0.f;
            #pragma unroll 8
            for (int j = 0; j < 64; j++)
                acc += s_A[il * 64 + j] * s_v[j * 64 + v];
            d_O[(tok0 + i) * VDn + h * HVn + v] = acc;
        }
    }
}

// ---------------- attention phase B: serial state scan per (b,h) --------------------
__global__ __launch_bounds__(512) void scan_kernel()
{
    const int bh = blockIdx.x;
    const int t = threadIdx.x;     // 512 threads, 4 elems each (2048 state elems)
    float S[4] = {0.f, 0.f, 0.f, 0.f};
    for (int c = 0; c < NC; c++) {
        const int ch = c * 32 + bh;
        const size_t base = (size_t)ch * 2048;
        #pragma unroll
        for (int e = 0; e < 4; e++) {
            int idx = e * 512 + t;
            d_Sb[base + idx] = S[e];                        // state BEFORE this chunk
            float dl = d_dl[ch * 32 + (idx >> 6)];
            S[e] = dl * S[e] + d_M[base + idx];
        }
    }
}

// ---------------- attention phase C: inter-chunk + RMSNorm + SiLU gate --------------
__global__ __launch_bounds__(256) void attn_inter_kernel(const float* __restrict__ norm_w)
{
    __shared__ float s_qe[2048];
    __shared__ float s_S[2048];
    __shared__ float red[8];

    const int cb = blockIdx.x;
    const int bh = cb & 31, c = cb >> 5;
    const int b = bh >> 4, h = bh & 15;
    const int t = threadIdx.x;
    const size_t tok0 = (size_t)b * Tn + (size_t)c * CHUNKn;

    for (int e = t; e < 2048; e += 256)
        s_qe[e] = d_GK[(tok0 + (e >> 5)) * KDn + h * HKn + (e & 31)];
    for (int e = t; e < 2048; e += 256)
        s_S[e] = d_Sb[(size_t)cb * 2048 + e];
    __syncthreads();
    if (t < 32) {
        float run = 0.f;
        for (int i = 0; i < 64; i++) { run += s_qe[i * 32 + t]; s_qe[i * 32 + t] = run; }
    }
    __syncthreads();
    for (int e = t; e < 2048; e += 256) {
        float bb = s_qe[e];
        float qv = d_Q[(tok0 + (e >> 5)) * KDn + h * HKn + (e & 31)];
        s_qe[e] = qv * expf(bb) * SCALE_Q;
    }
    __syncthreads();

    const int wid = t >> 5;
    for (int r = 0; r < 16; r++) {
        int o = t + 256 * r;
        int i = o >> 6, v = o & 63;
        size_t gi = (tok0 + i) * VDn + h * HVn + v;
        float acc = d_O[gi];                 // o_intra from phase A
        #pragma unroll
        for (int k = 0; k < 32; k++)
            acc += s_qe[i * 32 + k] * s_S[k * 64 + v];
        // RMS over the 64 v-lanes of this row (these 64 threads = 2 warps)
        float ss = acc * acc;
        #pragma unroll
        for (int off = 16; off > 0; off >>= 1)
            ss += __shfl_xor_sync(0xffffffffu, ss, off);
        if ((t & 31) == 0) red[wid] = ss;
        __syncthreads();
        float rowss = red[(t >> 6) * 2] + red[(t >> 6) * 2 + 1];
        __syncthreads();
        float rinv = rsqrtf(rowss * (1.f / 64.f) + 1e-5f);
        float g = d_Gb[gi];
        float sg = 1.f / (1.f + expf(-g));
        d_O[gi] = acc * rinv * norm_w[v] * (g * sg);
    }
}

// ---------------- launch ----------------
extern "C" void kernel_launch(void* const* d_in, const int* in_sizes, int n_in,
                              void* d_out, int out_size)
{
    const float* x      = (const float*)d_in[0];
    const float* Wq     = (const float*)d_in[1];
    const float* Wk     = (const float*)d_in[2];
    const float* Wv     = (const float*)d_in[3];
    const float* Wgk1   = (const float*)d_in[4];
    const float* Wgk2   = (const float*)d_in[5];
    const float* bgk    = (const float*)d_in[6];
    const float* Wg     = (const float*)d_in[7];
    const float* norm_w = (const float*)d_in[8];
    const float* Wo     = (const float*)d_in[9];
    float* out = (float*)d_out;

    float *pQ, *pK, *pV, *pG, *pO;
    cudaGetSymbolAddress((void**)&pQ, d_Q);
    cudaGetSymbolAddress((void**)&pK, d_Kb);
    cudaGetSymbolAddress((void**)&pV, d_Vb);
    cudaGetSymbolAddress((void**)&pG, d_Gb);
    cudaGetSymbolAddress((void**)&pO, d_O);

    // projections
    sgemm128<<<dim3(KDn / 128, NTOK / 128), 256>>>(x, Wq, pQ, NTOK, KDn, Dn);
    sgemm128<<<dim3(KDn / 128, NTOK / 128), 256>>>(x, Wk, pK, NTOK, KDn, Dn);
    sgemm128<<<dim3(VDn / 128, NTOK / 128), 256>>>(x, Wv, pV, NTOK, VDn, Dn);
    sgemm128<<<dim3(VDn / 128, NTOK / 128), 256>>>(x, Wg, pG, NTOK, VDn, Dn);

    // gate path
    gemm_gk1<<<NTOK, 256>>>(x, Wgk1);
    gk_kernel<<<(NTOK * KDn) / 256, 256>>>(Wgk2, bgk);

    // chunked linear attention, 3 phases
    attn_chunk_kernel<<<NCB, 256>>>();
    scan_kernel<<<BH, 512>>>();
    attn_inter_kernel<<<NCB, 256>>>(norm_w);

    // output projection
    sgemm128<<<dim3(Dn / 128, NTOK / 128), 256>>>(pO, Wo, out, NTOK, Dn, Dn);
}

// round 4
// speedup vs baseline: 1.5192x; 1.5192x over previous
#include <cuda_runtime.h>
#include <cuda_bf16.h>
#include <math.h>
#include <cstdint>

// ---------------- problem constants ----------------
#define Bn 2
#define Tn 4096
#define Dn 1024
#define Hn 16
#define KDn 512
#define VDn 1024
#define HKn 32
#define HVn 64
#define CHUNKn 64
#define NC (Tn / CHUNKn)          // 64 chunks
#define NTOK (Bn * Tn)            // 8192 tokens
#define BH (Bn * Hn)              // 32
#define NCB (NC * BH)             // 2048 chunk-heads
#define SCALE_Q 0.17677669529663687f  // 1/sqrt(32)

// ---------------- scratch (static device globals; no allocation) ----------------
__device__ float d_Q[NTOK * KDn];        // 16 MB
__device__ float d_Kb[NTOK * KDn];       // 16 MB
__device__ float d_Vb[NTOK * VDn];       // 32 MB
__device__ float d_Gb[NTOK * VDn];       // 32 MB
__device__ float d_GK[NTOK * KDn];       // 16 MB
__device__ float d_t16[NTOK * 16];       // 0.5 MB
__device__ float d_M[NCB * HKn * HVn];   // 16 MB
__device__ float d_Sb[NCB * HKn * HVn];  // 16 MB
__device__ float d_dl[NCB * HKn];        // 0.25 MB
__device__ float d_O[NTOK * VDn];        // 32 MB
__device__ float d_Xr[NTOK * Dn];        // 32 MB   x rounded to tf32
__device__ float d_WqT[KDn * Dn];        // 2 MB    transposed+rounded weights
__device__ float d_WkT[KDn * Dn];        // 2 MB
__device__ float d_WvT[VDn * Dn];        // 4 MB
__device__ float d_WgT[VDn * Dn];        // 4 MB
__device__ float d_WoT[Dn * Dn];         // 4 MB

// ---------------- helpers ----------------
__device__ __forceinline__ float rtf32(float x) {   // round-to-nearest tf32 (unbiased)
    uint32_t r;
    asm("cvt.rna.tf32.f32 %0, %1;" : "=r"(r) : "f"(x));
    return __uint_as_float(r);
}
// word index of element [r][k] in a 128-row x 32-col tile with SW128 xor swizzle
__device__ __forceinline__ int swzi(int r, int k) {
    int o = (r << 7) + (k << 2);
    return (o ^ ((o >> 3) & 0x70)) >> 2;
}
__device__ __forceinline__ void mma_tf32(float* c, const uint32_t* a, const uint32_t* b) {
    asm volatile(
        "mma.sync.aligned.m16n8k8.row.col.f32.tf32.tf32.f32 "
        "{%0,%1,%2,%3}, {%4,%5,%6,%7}, {%8,%9}, {%0,%1,%2,%3};"
        : "+f"(c[0]), "+f"(c[1]), "+f"(c[2]), "+f"(c[3])
        : "r"(a[0]), "r"(a[1]), "r"(a[2]), "r"(a[3]), "r"(b[0]), "r"(b[1]));
}

// ---------------- tf32 tensor-core GEMM: C[M,N] = A[M,K] * BT[N,K]^T ----------------
// Both operands K-major, pre-rounded to tf32. Tile 128x128, K-step 32,
// 4-stage cp.async pipeline, SW128 xor swizzle, mma.sync m16n8k8.
#define GST 4
#define STAGE_BYTES 32768   // A 16KB + B 16KB
#define GEMM_DYNSMEM (GST * STAGE_BYTES)

__global__ __launch_bounds__(256) void gemm_tf32(
    const float* __restrict__ A, const float* __restrict__ BT,
    float* __restrict__ C, int M, int N, int K)
{
    extern __shared__ __align__(16) char dyn[];
    uint32_t sbase;
    asm("{ .reg .u64 t; cvta.to.shared.u64 t, %1; cvt.u32.u64 %0, t; }"
        : "=r"(sbase) : "l"(dyn));
    const int t = threadIdx.x;
    const int lane = t & 31;
    const int wrow = (t >> 5) >> 2;   // 0..1  (64 rows each)
    const int wcol = (t >> 5) & 3;    // 0..3  (32 cols each)
    const int bm = blockIdx.y << 7, bn = blockIdx.x << 7;
    const int NT = K >> 5;

    #define LOAD_TILE(kt)                                                              \
    do {                                                                               \
        const int k0_ = (kt) << 5;                                                     \
        const uint32_t stg_ = sbase + ((kt) & (GST - 1)) * STAGE_BYTES;                \
        _Pragma("unroll")                                                              \
        for (int i_ = 0; i_ < 4; i_++) {                                               \
            int q_ = t + (i_ << 8);                                                    \
            int row_ = q_ >> 3, c16_ = q_ & 7;                                         \
            const float* g_ = A + (size_t)(bm + row_) * K + k0_ + (c16_ << 2);         \
            uint32_t off_ = (uint32_t)((row_ << 7) + (c16_ << 4));                     \
            uint32_t dst_ = stg_ + (off_ ^ ((off_ >> 3) & 0x70));                      \
            asm volatile("cp.async.cg.shared.global [%0], [%1], 16;" :: "r"(dst_), "l"(g_)); \
        }                                                                              \
        _Pragma("unroll")                                                              \
        for (int i_ = 4; i_ < 8; i_++) {                                               \
            int q_ = t + (i_ << 8) - 1024;                                             \
            int row_ = q_ >> 3, c16_ = q_ & 7;                                         \
            const float* g_ = BT + (size_t)(bn + row_) * K + k0_ + (c16_ << 2);        \
            uint32_t off_ = (uint32_t)((row_ << 7) + (c16_ << 4));                     \
            uint32_t dst_ = stg_ + 16384 + (off_ ^ ((off_ >> 3) & 0x70));              \
            asm volatile("cp.async.cg.shared.global [%0], [%1], 16;" :: "r"(dst_), "l"(g_)); \
        }                                                                              \
        asm volatile("cp.async.commit_group;");                                        \
    } while (0)

    float acc[4][4][4];
    #pragma unroll
    for (int i = 0; i < 4; i++)
        #pragma unroll
        for (int j = 0; j < 4; j++)
            #pragma unroll
            for (int e = 0; e < 4; e++) acc[i][j][e] = 0.f;

    // prologue
    for (int s = 0; s < GST - 1; s++) LOAD_TILE(s);

    for (int kt = 0; kt < NT; kt++) {
        asm volatile("cp.async.wait_group %0;" :: "n"(GST - 2));
        __syncthreads();
        // issue next tile's loads (overwrites buffer consumed at iter kt-1;
        // the syncthreads above guarantees everyone finished it)
        const int nt_ = kt + GST - 1;
        if (nt_ < NT) LOAD_TILE(nt_);

        const float* sA = (const float*)(dyn + (kt & (GST - 1)) * STAGE_BYTES);
        const float* sB = (const float*)(dyn + (kt & (GST - 1)) * STAGE_BYTES + 16384);

        #pragma unroll
        for (int ks = 0; ks < 4; ks++) {
            const int kc = (ks << 3) + (lane & 3);
            uint32_t af[4][4], bf[4][2];
            #pragma unroll
            for (int mt = 0; mt < 4; mt++) {
                int r = wrow * 64 + mt * 16 + (lane >> 2);
                af[mt][0] = __float_as_uint(sA[swzi(r,     kc)]);
                af[mt][1] = __float_as_uint(sA[swzi(r + 8, kc)]);
                af[mt][2] = __float_as_uint(sA[swzi(r,     kc + 4)]);
                af[mt][3] = __float_as_uint(sA[swzi(r + 8, kc + 4)]);
            }
            #pragma unroll
            for (int nt = 0; nt < 4; nt++) {
                int n = wcol * 32 + nt * 8 + (lane >> 2);
                bf[nt][0] = __float_as_uint(sB[swzi(n, kc)]);
                bf[nt][1] = __float_as_uint(sB[swzi(n, kc + 4)]);
            }
            #pragma unroll
            for (int mt = 0; mt < 4; mt++)
                #pragma unroll
                for (int nt = 0; nt < 4; nt++)
                    mma_tf32(acc[mt][nt], af[mt], bf[nt]);
        }
    }

    // epilogue: direct register -> global stores (float2 per c-pair)
    #pragma unroll
    for (int mt = 0; mt < 4; mt++) {
        #pragma unroll
        for (int nt = 0; nt < 4; nt++) {
            int r0 = bm + wrow * 64 + mt * 16 + (lane >> 2);
            int c0 = bn + wcol * 32 + nt * 8 + (lane & 3) * 2;
            float2 v0 = make_float2(acc[mt][nt][0], acc[mt][nt][1]);
            float2 v1 = make_float2(acc[mt][nt][2], acc[mt][nt][3]);
            *(float2*)&C[(size_t)r0 * N + c0] = v0;
            *(float2*)&C[(size_t)(r0 + 8) * N + c0] = v1;
        }
    }
}

// ---------------- pre-passes: tf32 rounding + weight transpose ----------------
__global__ __launch_bounds__(256) void round_x_kernel(const float* __restrict__ X,
                                                      float* __restrict__ Y)
{
    int i = blockIdx.x * 256 + threadIdx.x;   // over float4s
    float4 v = ((const float4*)X)[i];
    v.x = rtf32(v.x); v.y = rtf32(v.y); v.z = rtf32(v.z); v.w = rtf32(v.w);
    ((float4*)Y)[i] = v;
}

__global__ __launch_bounds__(256) void transpose_rt(const float* __restrict__ W,
                                                    float* __restrict__ WT,
                                                    int Kd, int Nd)
{
    __shared__ float tl[32][33];
    int n0 = blockIdx.x * 32, k0 = blockIdx.y * 32;
    int tx = threadIdx.x & 31, ty = threadIdx.x >> 5;   // 32x8
    #pragma unroll
    for (int r = 0; r < 32; r += 8)
        tl[ty + r][tx] = W[(size_t)(k0 + ty + r) * Nd + n0 + tx];
    __syncthreads();
    #pragma unroll
    for (int r = 0; r < 32; r += 8)
        WT[(size_t)(n0 + ty + r) * Kd + k0 + tx] = rtf32(tl[tx][ty + r]);
}

// ---------------- gk low-rank stage 1: t16 = x @ Wgk1 ----------
__global__ __launch_bounds__(256) void gemm_gk1(const float* __restrict__ X,
                                                const float* __restrict__ W)
{
    __shared__ float red[256];
    const int m = blockIdx.x;
    const int tx = threadIdx.x & 15;
    const int ty = threadIdx.x >> 4;
    float acc = 0.f;
    const float* xr = X + (size_t)m * Dn;
    for (int k = ty; k < Dn; k += 16)
        acc += xr[k] * W[k * 16 + tx];
    red[threadIdx.x] = acc;
    __syncthreads();
    for (int s = 8; s > 0; s >>= 1) {
        if (ty < s) red[ty * 16 + tx] += red[(ty + s) * 16 + tx];
        __syncthreads();
    }
    if (ty == 0) d_t16[m * 16 + tx] = red[tx];
}

// ---------------- gk stage 2 ----------------
__global__ __launch_bounds__(256) void gk_kernel(const float* __restrict__ W2,
                                                 const float* __restrict__ bgk)
{
    int idx = blockIdx.x * blockDim.x + threadIdx.x;
    int m = idx >> 9;
    int n = idx & 511;
    const float* t = d_t16 + m * 16;
    float z = bgk[n];
    #pragma unroll
    for (int k = 0; k < 16; k++) z += t[k] * W2[k * KDn + n];
    float ls = fminf(z, 0.f) - log1pf(expf(-fabsf(z)));
    d_GK[idx] = ls * (1.f / 16.f);
}

// ---------------- attention phase A ----------------
__global__ __launch_bounds__(256) void attn_chunk_kernel()
{
    __shared__ float s_qe[2048];
    __shared__ float s_kd[2048];
    __shared__ float s_v[4096];
    __shared__ float s_A[2048];
    __shared__ float s_bl[32], s_dl[32];

    const int cb = blockIdx.x;
    const int bh = cb & 31, c = cb >> 5;
    const int b = bh >> 4, h = bh & 15;
    const int t = threadIdx.x;
    const size_t tok0 = (size_t)b * Tn + (size_t)c * CHUNKn;

    for (int e = t; e < 2048; e += 256) {
        int i = e >> 5, k = e & 31;
        s_qe[e] = d_GK[(tok0 + i) * KDn + h * HKn + k];
    }
    __syncthreads();
    if (t < 32) {
        float run = 0.f;
        for (int i = 0; i < 64; i++) { run += s_qe[i * 32 + t]; s_qe[i * 32 + t] = run; }
        s_bl[t] = run;
        s_dl[t] = expf(run);
    }
    __syncthreads();
    for (int e = t; e < 2048; e += 256) {
        int i = e >> 5, k = e & 31;
        float bb = s_qe[e];
        float kv = d_Kb[(tok0 + i) * KDn + h * HKn + k];
        s_kd[i * 32 + ((k ^ i) & 31)] = kv * expf(-bb);
        float qv = d_Q[(tok0 + i) * KDn + h * HKn + k];
        s_qe[e] = qv * expf(bb) * SCALE_Q;
    }
    for (int e = t; e < 4096; e += 256) {
        int i = e >> 6, v = e & 63;
        s_v[e] = d_Vb[(tok0 + i) * VDn + h * HVn + v];
    }
    __syncthreads();
    for (int o = t; o < 2048; o += 256) {
        int k = o >> 6, v = o & 63;
        float acc = 0.f;
        #pragma unroll 8
        for (int j = 0; j < 64; j++)
            acc += s_kd[j * 32 + ((k ^ j) & 31)] * s_v[j * 64 + v];
        d_M[(size_t)cb * 2048 + o] = acc * s_dl[k];
    }
    if (t < 32) d_dl[cb * 32 + t] = s_dl[t];

    #pragma unroll
    for (int half = 0; half < 2; half++) {
        __syncthreads();
        for (int o = t; o < 2048; o += 256) {
            int il = o >> 6, j = o & 63;
            int i = half * 32 + il;
            float acc = 0.f;
            if (j <= i) {
                #pragma unroll
                for (int k = 0; k < 32; k++)
                    acc += s_qe[i * 32 + k] * s_kd[j * 32 + ((k ^ j) & 31)];
            }
            s_A[o] = acc;
        }
        __syncthreads();
        for (int o = t; o < 2048; o += 256) {
            int il = o >> 6, v = o & 63;
            int i = half * 32 + il;
            float acc = 0.f;
            #pragma unroll 8
            for (int j = 0; j < 64; j++)
                acc += s_A[il * 64 + j] * s_v[j * 64 + v];
            d_O[(tok0 + i) * VDn + h * HVn + v] = acc;
        }
    }
}

// ---------------- attention phase B: serial state scan ----------------
__global__ __launch_bounds__(512) void scan_kernel()
{
    const int bh = blockIdx.x;
    const int t = threadIdx.x;
    float S[4] = {0.f, 0.f, 0.f, 0.f};
    for (int c = 0; c < NC; c++) {
        const int ch = c * 32 + bh;
        const size_t base = (size_t)ch * 2048;
        #pragma unroll
        for (int e = 0; e < 4; e++) {
            int idx = e * 512 + t;
            d_Sb[base + idx] = S[e];
            float dl = d_dl[ch * 32 + (idx >> 6)];
            S[e] = dl * S[e] + d_M[base + idx];
        }
    }
}

// ---------------- attention phase C: inter-chunk + RMSNorm + SiLU gate ------------
// Final store rounded to tf32 (it feeds the Wo tensor-core GEMM).
__global__ __launch_bounds__(256) void attn_inter_kernel(const float* __restrict__ norm_w)
{
    __shared__ float s_qe[2048];
    __shared__ float s_S[2048];
    __shared__ float red[8];

    const int cb = blockIdx.x;
    const int bh = cb & 31, c = cb >> 5;
    const int b = bh >> 4, h = bh & 15;
    const int t = threadIdx.x;
    const size_t tok0 = (size_t)b * Tn + (size_t)c * CHUNKn;

    for (int e = t; e < 2048; e += 256)
        s_qe[e] = d_GK[(tok0 + (e >> 5)) * KDn + h * HKn + (e & 31)];
    for (int e = t; e < 2048; e += 256)
        s_S[e] = d_Sb[(size_t)cb * 2048 + e];
    __syncthreads();
    if (t < 32) {
        float run = 0.f;
        for (int i = 0; i < 64; i++) { run += s_qe[i * 32 + t]; s_qe[i * 32 + t] = run; }
    }
    __syncthreads();
    for (int e = t; e < 2048; e += 256) {
        float bb = s_qe[e];
        float qv = d_Q[(tok0 + (e >> 5)) * KDn + h * HKn + (e & 31)];
        s_qe[e] = qv * expf(bb) * SCALE_Q;
    }
    __syncthreads();

    const int wid = t >> 5;
    for (int r = 0; r < 16; r++) {
        int o = t + 256 * r;
        int i = o >> 6, v = o & 63;
        size_t gi = (tok0 + i) * VDn + h * HVn + v;
        float acc = d_O[gi];
        #pragma unroll
        for (int k = 0; k < 32; k++)
            acc += s_qe[i * 32 + k] * s_S[k * 64 + v];
        float ss = acc * acc;
        #pragma unroll
        for (int off = 16; off > 0; off >>= 1)
            ss += __shfl_xor_sync(0xffffffffu, ss, off);
        if ((t & 31) == 0) red[wid] = ss;
        __syncthreads();
        float rowss = red[(t >> 6) * 2] + red[(t >> 6) * 2 + 1];
        __syncthreads();
        float rinv = rsqrtf(rowss * (1.f / 64.f) + 1e-5f);
        float g = d_Gb[gi];
        float sg = 1.f / (1.f + expf(-g));
        d_O[gi] = rtf32(acc * rinv * norm_w[v] * (g * sg));
    }
}

// ---------------- launch ----------------
extern "C" void kernel_launch(void* const* d_in, const int* in_sizes, int n_in,
                              void* d_out, int out_size)
{
    const float* x      = (const float*)d_in[0];
    const float* Wq     = (const float*)d_in[1];
    const float* Wk     = (const float*)d_in[2];
    const float* Wv     = (const float*)d_in[3];
    const float* Wgk1   = (const float*)d_in[4];
    const float* Wgk2   = (const float*)d_in[5];
    const float* bgk    = (const float*)d_in[6];
    const float* Wg     = (const float*)d_in[7];
    const float* norm_w = (const float*)d_in[8];
    const float* Wo     = (const float*)d_in[9];
    float* out = (float*)d_out;

    float *pQ, *pK, *pV, *pG, *pO, *pXr, *pWqT, *pWkT, *pWvT, *pWgT, *pWoT;
    cudaGetSymbolAddress((void**)&pQ, d_Q);
    cudaGetSymbolAddress((void**)&pK, d_Kb);
    cudaGetSymbolAddress((void**)&pV, d_Vb);
    cudaGetSymbolAddress((void**)&pG, d_Gb);
    cudaGetSymbolAddress((void**)&pO, d_O);
    cudaGetSymbolAddress((void**)&pXr, d_Xr);
    cudaGetSymbolAddress((void**)&pWqT, d_WqT);
    cudaGetSymbolAddress((void**)&pWkT, d_WkT);
    cudaGetSymbolAddress((void**)&pWvT, d_WvT);
    cudaGetSymbolAddress((void**)&pWgT, d_WgT);
    cudaGetSymbolAddress((void**)&pWoT, d_WoT);

    cudaFuncSetAttribute(gemm_tf32, cudaFuncAttributeMaxDynamicSharedMemorySize,
                         GEMM_DYNSMEM);

    // pre-passes: tf32 rounding + weight transposes
    round_x_kernel<<<(NTOK * Dn / 4) / 256, 256>>>(x, pXr);
    transpose_rt<<<dim3(KDn / 32, Dn / 32), 256>>>(Wq, pWqT, Dn, KDn);
    transpose_rt<<<dim3(KDn / 32, Dn / 32), 256>>>(Wk, pWkT, Dn, KDn);
    transpose_rt<<<dim3(VDn / 32, Dn / 32), 256>>>(Wv, pWvT, Dn, VDn);
    transpose_rt<<<dim3(VDn / 32, Dn / 32), 256>>>(Wg, pWgT, Dn, VDn);
    transpose_rt<<<dim3(Dn / 32, VDn / 32), 256>>>(Wo, pWoT, VDn, Dn);

    // projections on tensor cores (tf32 mma.sync)
    gemm_tf32<<<dim3(KDn / 128, NTOK / 128), 256, GEMM_DYNSMEM>>>(pXr, pWqT, pQ, NTOK, KDn, Dn);
    gemm_tf32<<<dim3(KDn / 128, NTOK / 128), 256, GEMM_DYNSMEM>>>(pXr, pWkT, pK, NTOK, KDn, Dn);
    gemm_tf32<<<dim3(VDn / 128, NTOK / 128), 256, GEMM_DYNSMEM>>>(pXr, pWvT, pV, NTOK, VDn, Dn);
    gemm_tf32<<<dim3(VDn / 128, NTOK / 128), 256, GEMM_DYNSMEM>>>(pXr, pWgT, pG, NTOK, VDn, Dn);

    // gate path
    gemm_gk1<<<NTOK, 256>>>(x, Wgk1);
    gk_kernel<<<(NTOK * KDn) / 256, 256>>>(Wgk2, bgk);

    // chunked linear attention
    attn_chunk_kernel<<<NCB, 256>>>();
    scan_kernel<<<BH, 512>>>();
    attn_inter_kernel<<<NCB, 256>>>(norm_w);

    // output projection
    gemm_tf32<<<dim3(Dn / 128, NTOK / 128), 256, GEMM_DYNSMEM>>>(pO, pWoT, out, NTOK, Dn, Dn);
}

// round 6
// speedup vs baseline: 2.4349x; 1.6027x over previous
#include <cuda_runtime.h>
#include <cuda_bf16.h>
#include <math.h>
#include <cstdint>

// ---------------- problem constants ----------------
#define Bn 2
#define Tn 4096
#define Dn 1024
#define Hn 16
#define KDn 512
#define VDn 1024
#define HKn 32
#define HVn 64
#define CHUNKn 64
#define NC (Tn / CHUNKn)          // 64 chunks
#define NTOK (Bn * Tn)            // 8192 tokens
#define BH (Bn * Hn)              // 32
#define NCB (NC * BH)             // 2048 chunk-heads
#define SCALE_Q 0.17677669529663687f  // 1/sqrt(32)

// ---------------- scratch (static device globals; no allocation) ----------------
__device__ float d_Q[NTOK * KDn];        // 16 MB
__device__ float d_Kb[NTOK * KDn];       // 16 MB
__device__ float d_Vb[NTOK * VDn];       // 32 MB
__device__ float d_Gb[NTOK * VDn];       // 32 MB
__device__ float d_GK[NTOK * KDn];       // 16 MB
__device__ float d_t16[NTOK * 16];       // 0.5 MB
__device__ float d_M[NCB * HKn * HVn];   // 16 MB
__device__ float d_Sb[NCB * HKn * HVn];  // 16 MB
__device__ float d_dl[NCB * HKn];        // 0.25 MB
__device__ float d_O[NTOK * VDn];        // 32 MB
__device__ float d_Xr[NTOK * Dn];        // 32 MB   x rounded to tf32
__device__ float d_WqT[KDn * Dn];        // 2 MB    transposed+rounded weights
__device__ float d_WkT[KDn * Dn];        // 2 MB
__device__ float d_WvT[VDn * Dn];        // 4 MB
__device__ float d_WgT[VDn * Dn];        // 4 MB
__device__ float d_WoT[Dn * Dn];         // 4 MB

// ---------------- helpers ----------------
__device__ __forceinline__ float rtf32(float x) {   // round-to-nearest tf32 (unbiased)
    uint32_t r;
    asm("cvt.rna.tf32.f32 %0, %1;" : "=r"(r) : "f"(x));
    return __uint_as_float(r);
}
__device__ __forceinline__ void mma_tf32(float* c, const uint32_t* a, const uint32_t* b) {
    asm volatile(
        "mma.sync.aligned.m16n8k8.row.col.f32.tf32.tf32.f32 "
        "{%0,%1,%2,%3}, {%4,%5,%6,%7}, {%8,%9}, {%0,%1,%2,%3};"
        : "+f"(c[0]), "+f"(c[1]), "+f"(c[2]), "+f"(c[3])
        : "r"(a[0]), "r"(a[1]), "r"(a[2]), "r"(a[3]), "r"(b[0]), "r"(b[1]));
}
// ldmatrix: a 16x8 tf32 fragment is byte-identical to four 8x8 b16 matrices.
__device__ __forceinline__ void ldsm_x4(uint32_t* d, uint32_t addr) {
    asm volatile("ldmatrix.sync.aligned.m8n8.x4.shared.b16 {%0,%1,%2,%3}, [%4];"
        : "=r"(d[0]), "=r"(d[1]), "=r"(d[2]), "=r"(d[3]) : "r"(addr));
}
__device__ __forceinline__ void ldsm_x2(uint32_t* d, uint32_t addr) {
    asm volatile("ldmatrix.sync.aligned.m8n8.x2.shared.b16 {%0,%1}, [%2];"
        : "=r"(d[0]), "=r"(d[1]) : "r"(addr));
}

// ---------------- tf32 tensor-core GEMM: C[M,N] = A[M,K] * BT[N,K]^T ----------------
// Both operands K-major, pre-rounded to tf32. Tile 128x128, K-step 32,
// 3-stage cp.async pipeline (96KB smem -> 2 CTAs/SM), SW128 xor swizzle,
// ldmatrix fragment loads, mma.sync m16n8k8.
#define GST 3
#define STAGE_BYTES 32768   // A 16KB + B 16KB
#define GEMM_DYNSMEM (GST * STAGE_BYTES)

__global__ __launch_bounds__(256, 2) void gemm_tf32(
    const float* __restrict__ A, const float* __restrict__ BT,
    float* __restrict__ C, int M, int N, int K)
{
    extern __shared__ __align__(16) char dyn[];
    uint32_t sbase;
    asm("{ .reg .u64 t; cvta.to.shared.u64 t, %1; cvt.u32.u64 %0, t; }"
        : "=r"(sbase) : "l"(dyn));
    const int t = threadIdx.x;
    const int lane = t & 31;
    const int wrow = (t >> 5) >> 2;   // 0..1  (64 rows each)
    const int wcol = (t >> 5) & 3;    // 0..3  (32 cols each)
    const int bm = blockIdx.y << 7, bn = blockIdx.x << 7;
    const int NT = K >> 5;

    // per-lane ldmatrix address components (byte offsets inside a 128-row x 32-col
    // tile, 128B per row).
    // x4 matrix order must be (r0,+0B),(r0+8,+0B),(r0,+16B),(r0+8,+16B) to map to
    // tf32 A-fragment {a0,a1,a2,a3}:
    //   lanes 8-15  -> matrix 1 -> rows +8, byte +0   -> (lane>>3)&1 drives +8 rows
    //   lanes 16-23 -> matrix 2 -> rows +0, byte +16  -> (lane>>4)&1 drives +16 bytes
    const int aoff = (wrow * 64 + ((lane >> 3) & 1) * 8 + (lane & 7)) * 128
                   + ((lane >> 4) & 1) * 16;              // + mt*2048 + ks*32
    const int boff = (wcol * 32 + (lane & 7)) * 128
                   + ((lane >> 3) & 1) * 16;              // + nt*1024 + ks*32

    #define LOAD_TILE(kt)                                                              \
    do {                                                                               \
        const int k0_ = (kt) << 5;                                                     \
        const uint32_t stg_ = sbase + ((kt) % GST) * STAGE_BYTES;                      \
        _Pragma("unroll")                                                              \
        for (int i_ = 0; i_ < 4; i_++) {                                               \
            int q_ = t + (i_ << 8);                                                    \
            int row_ = q_ >> 3, c16_ = q_ & 7;                                         \
            const float* g_ = A + (size_t)(bm + row_) * K + k0_ + (c16_ << 2);         \
            uint32_t off_ = (uint32_t)((row_ << 7) + (c16_ << 4));                     \
            uint32_t dst_ = stg_ + (off_ ^ ((off_ >> 3) & 0x70));                      \
            asm volatile("cp.async.cg.shared.global [%0], [%1], 16;" :: "r"(dst_), "l"(g_)); \
        }                                                                              \
        _Pragma("unroll")                                                              \
        for (int i_ = 4; i_ < 8; i_++) {                                               \
            int q_ = t + (i_ << 8) - 1024;                                             \
            int row_ = q_ >> 3, c16_ = q_ & 7;                                         \
            const float* g_ = BT + (size_t)(bn + row_) * K + k0_ + (c16_ << 2);        \
            uint32_t off_ = (uint32_t)((row_ << 7) + (c16_ << 4));                     \
            uint32_t dst_ = stg_ + 16384 + (off_ ^ ((off_ >> 3) & 0x70));              \
            asm volatile("cp.async.cg.shared.global [%0], [%1], 16;" :: "r"(dst_), "l"(g_)); \
        }                                                                              \
        asm volatile("cp.async.commit_group;");                                        \
    } while (0)

    float acc[4][4][4];
    #pragma unroll
    for (int i = 0; i < 4; i++)
        #pragma unroll
        for (int j = 0; j < 4; j++)
            #pragma unroll
            for (int e = 0; e < 4; e++) acc[i][j][e] = 0.f;

    // prologue: 2 tiles in flight
    LOAD_TILE(0);
    LOAD_TILE(1);

    for (int kt = 0; kt < NT; kt++) {
        asm volatile("cp.async.wait_group %0;" :: "n"(GST - 2));   // tile kt resident
        __syncthreads();
        const int nt_ = kt + GST - 1;
        if (nt_ < NT) LOAD_TILE(nt_);   // overwrites buffer consumed at iter kt-1

        const uint32_t sAb = sbase + (kt % GST) * STAGE_BYTES;
        const uint32_t sBb = sAb + 16384;

        #pragma unroll
        for (int ks = 0; ks < 4; ks++) {
            uint32_t af[4][4], bf[4][2];
            #pragma unroll
            for (int mt = 0; mt < 4; mt++) {
                int o = aoff + mt * 2048 + ks * 32;
                ldsm_x4(af[mt], sAb + (o ^ ((o >> 3) & 0x70)));
            }
            #pragma unroll
            for (int nt = 0; nt < 4; nt++) {
                int o = boff + nt * 1024 + ks * 32;
                ldsm_x2(bf[nt], sBb + (o ^ ((o >> 3) & 0x70)));
            }
            #pragma unroll
            for (int mt = 0; mt < 4; mt++)
                #pragma unroll
                for (int nt = 0; nt < 4; nt++)
                    mma_tf32(acc[mt][nt], af[mt], bf[nt]);
        }
    }

    // epilogue: direct register -> global stores (float2 per c-pair)
    #pragma unroll
    for (int mt = 0; mt < 4; mt++) {
        #pragma unroll
        for (int nt = 0; nt < 4; nt++) {
            int r0 = bm + wrow * 64 + mt * 16 + (lane >> 2);
            int c0 = bn + wcol * 32 + nt * 8 + (lane & 3) * 2;
            float2 v0 = make_float2(acc[mt][nt][0], acc[mt][nt][1]);
            float2 v1 = make_float2(acc[mt][nt][2], acc[mt][nt][3]);
            *(float2*)&C[(size_t)r0 * N + c0] = v0;
            *(float2*)&C[(size_t)(r0 + 8) * N + c0] = v1;
        }
    }
}

// ---------------- pre-passes: tf32 rounding + weight transpose ----------------
__global__ __launch_bounds__(256) void round_x_kernel(const float* __restrict__ X,
                                                      float* __restrict__ Y)
{
    int i = blockIdx.x * 256 + threadIdx.x;   // over float4s
    float4 v = ((const float4*)X)[i];
    v.x = rtf32(v.x); v.y = rtf32(v.y); v.z = rtf32(v.z); v.w = rtf32(v.w);
    ((float4*)Y)[i] = v;
}

__global__ __launch_bounds__(256) void transpose_rt(const float* __restrict__ W,
                                                    float* __restrict__ WT,
                                                    int Kd, int Nd)
{
    __shared__ float tl[32][33];
    int n0 = blockIdx.x * 32, k0 = blockIdx.y * 32;
    int tx = threadIdx.x & 31, ty = threadIdx.x >> 5;   // 32x8
    #pragma unroll
    for (int r = 0; r < 32; r += 8)
        tl[ty + r][tx] = W[(size_t)(k0 + ty + r) * Nd + n0 + tx];
    __syncthreads();
    #pragma unroll
    for (int r = 0; r < 32; r += 8)
        WT[(size_t)(n0 + ty + r) * Kd + k0 + tx] = rtf32(tl[tx][ty + r]);
}

// ---------------- gk low-rank stage 1: t16 = x @ Wgk1 ----------
__global__ __launch_bounds__(256) void gemm_gk1(const float* __restrict__ X,
                                                const float* __restrict__ W)
{
    __shared__ float red[256];
    const int m = blockIdx.x;
    const int tx = threadIdx.x & 15;
    const int ty = threadIdx.x >> 4;
    float acc = 0.f;
    const float* xr = X + (size_t)m * Dn;
    for (int k = ty; k < Dn; k += 16)
        acc += xr[k] * W[k * 16 + tx];
    red[threadIdx.x] = acc;
    __syncthreads();
    for (int s = 8; s > 0; s >>= 1) {
        if (ty < s) red[ty * 16 + tx] += red[(ty + s) * 16 + tx];
        __syncthreads();
    }
    if (ty == 0) d_t16[m * 16 + tx] = red[tx];
}

// ---------------- gk stage 2 ----------------
__global__ __launch_bounds__(256) void gk_kernel(const float* __restrict__ W2,
                                                 const float* __restrict__ bgk)
{
    int idx = blockIdx.x * blockDim.x + threadIdx.x;
    int m = idx >> 9;
    int n = idx & 511;
    const float* t = d_t16 + m * 16;
    float z = bgk[n];
    #pragma unroll
    for (int k = 0; k < 16; k++) z += t[k] * W2[k * KDn + n];
    float ls = fminf(z, 0.f) - log1pf(expf(-fabsf(z)));
    d_GK[idx] = ls * (1.f / 16.f);
}

// ---------------- attention phase A ----------------
__global__ __launch_bounds__(256) void attn_chunk_kernel()
{
    __shared__ float s_qe[2048];
    __shared__ float s_kd[2048];
    __shared__ float s_v[4096];
    __shared__ float s_A[2048];
    __shared__ float s_bl[32], s_dl[32];

    const int cb = blockIdx.x;
    const int bh = cb & 31, c = cb >> 5;
    const int b = bh >> 4, h = bh & 15;
    const int t = threadIdx.x;
    const size_t tok0 = (size_t)b * Tn + (size_t)c * CHUNKn;

    for (int e = t; e < 2048; e += 256) {
        int i = e >> 5, k = e & 31;
        s_qe[e] = d_GK[(tok0 + i) * KDn + h * HKn + k];
    }
    __syncthreads();
    if (t < 32) {
        float run = 0.f;
        for (int i = 0; i < 64; i++) { run += s_qe[i * 32 + t]; s_qe[i * 32 + t] = run; }
        s_bl[t] = run;
        s_dl[t] = expf(run);
    }
    __syncthreads();
    for (int e = t; e < 2048; e += 256) {
        int i = e >> 5, k = e & 31;
        float bb = s_qe[e];
        float kv = d_Kb[(tok0 + i) * KDn + h * HKn + k];
        s_kd[i * 32 + ((k ^ i) & 31)] = kv * expf(-bb);
        float qv = d_Q[(tok0 + i) * KDn + h * HKn + k];
        s_qe[e] = qv * expf(bb) * SCALE_Q;
    }
    for (int e = t; e < 4096; e += 256) {
        int i = e >> 6, v = e & 63;
        s_v[e] = d_Vb[(tok0 + i) * VDn + h * HVn + v];
    }
    __syncthreads();
    for (int o = t; o < 2048; o += 256) {
        int k = o >> 6, v = o & 63;
        float acc = 0.f;
        #pragma unroll 8
        for (int j = 0; j < 64; j++)
            acc += s_kd[j * 32 + ((k ^ j) & 31)] * s_v[j * 64 + v];
        d_M[(size_t)cb * 2048 + o] = acc * s_dl[k];
    }
    if (t < 32) d_dl[cb * 32 + t] = s_dl[t];

    #pragma unroll
    for (int half = 0; half < 2; half++) {
        __syncthreads();
        for (int o = t; o < 2048; o += 256) {
            int il = o >> 6, j = o & 63;
            int i = half * 32 + il;
            float acc = 0.f;
            if (j <= i) {
                #pragma unroll
                for (int k = 0; k < 32; k++)
                    acc += s_qe[i * 32 + k] * s_kd[j * 32 + ((k ^ j) & 31)];
            }
            s_A[o] = acc;
        }
        __syncthreads();
        for (int o = t; o < 2048; o += 256) {
            int il = o >> 6, v = o & 63;
            int i = half * 32 + il;
            float acc = 0.f;
            #pragma unroll 8
            for (int j = 0; j < 64; j++)
                acc += s_A[il * 64 + j] * s_v[j * 64 + v];
            d_O[(tok0 + i) * VDn + h * HVn + v] = acc;
        }
    }
}

// ---------------- attention phase B: serial state scan ----------------
__global__ __launch_bounds__(512) void scan_kernel()
{
    const int bh = blockIdx.x;
    const int t = threadIdx.x;
    float S[4] = {0.f, 0.f, 0.f, 0.f};
    for (int c = 0; c < NC; c++) {
        const int ch = c * 32 + bh;
        const size_t base = (size_t)ch * 2048;
        #pragma unroll
        for (int e = 0; e < 4; e++) {
            int idx = e * 512 + t;
            d_Sb[base + idx] = S[e];
            float dl = d_dl[ch * 32 + (idx >> 6)];
            S[e] = dl * S[e] + d_M[base + idx];
        }
    }
}

// ---------------- attention phase C: inter-chunk + RMSNorm + SiLU gate ------------
// Final store rounded to tf32 (it feeds the Wo tensor-core GEMM).
__global__ __launch_bounds__(256) void attn_inter_kernel(const float* __restrict__ norm_w)
{
    __shared__ float s_qe[2048];
    __shared__ float s_S[2048];
    __shared__ float red[8];

    const int cb = blockIdx.x;
    const int bh = cb & 31, c = cb >> 5;
    const int b = bh >> 4, h = bh & 15;
    const int t = threadIdx.x;
    const size_t tok0 = (size_t)b * Tn + (size_t)c * CHUNKn;

    for (int e = t; e < 2048; e += 256)
        s_qe[e] = d_GK[(tok0 + (e >> 5)) * KDn + h * HKn + (e & 31)];
    for (int e = t; e < 2048; e += 256)
        s_S[e] = d_Sb[(size_t)cb * 2048 + e];
    __syncthreads();
    if (t < 32) {
        float run = 0.f;
        for (int i = 0; i < 64; i++) { run += s_qe[i * 32 + t]; s_qe[i * 32 + t] = run; }
    }
    __syncthreads();
    for (int e = t; e < 2048; e += 256) {
        float bb = s_qe[e];
        float qv = d_Q[(tok0 + (e >> 5)) * KDn + h * HKn + (e & 31)];
        s_qe[e] = qv * expf(bb) * SCALE_Q;
    }
    __syncthreads();

    const int wid = t >> 5;
    for (int r = 0; r < 16; r++) {
        int o = t + 256 * r;
        int i = o >> 6, v = o & 63;
        size_t gi = (tok0 + i) * VDn + h * HVn + v;
        float acc = d_O[gi];
        #pragma unroll
        for (int k = 0; k < 32; k++)
            acc += s_qe[i * 32 + k] * s_S[k * 64 + v];
        float ss = acc * acc;
        #pragma unroll
        for (int off = 16; off > 0; off >>= 1)
            ss += __shfl_xor_sync(0xffffffffu, ss, off);
        if ((t & 31) == 0) red[wid] = ss;
        __syncthreads();
        float rowss = red[(t >> 6) * 2] + red[(t >> 6) * 2 + 1];
        __syncthreads();
        float rinv = rsqrtf(rowss * (1.f / 64.f) + 1e-5f);
        float g = d_Gb[gi];
        float sg = 1.f / (1.f + expf(-g));
        d_O[gi] = rtf32(acc * rinv * norm_w[v] * (g * sg));
    }
}

// ---------------- launch ----------------
extern "C" void kernel_launch(void* const* d_in, const int* in_sizes, int n_in,
                              void* d_out, int out_size)
{
    const float* x      = (const float*)d_in[0];
    const float* Wq     = (const float*)d_in[1];
    const float* Wk     = (const float*)d_in[2];
    const float* Wv     = (const float*)d_in[3];
    const float* Wgk1   = (const float*)d_in[4];
    const float* Wgk2   = (const float*)d_in[5];
    const float* bgk    = (const float*)d_in[6];
    const float* Wg     = (const float*)d_in[7];
    const float* norm_w = (const float*)d_in[8];
    const float* Wo     = (const float*)d_in[9];
    float* out = (float*)d_out;

    float *pQ, *pK, *pV, *pG, *pO, *pXr, *pWqT, *pWkT, *pWvT, *pWgT, *pWoT;
    cudaGetSymbolAddress((void**)&pQ, d_Q);
    cudaGetSymbolAddress((void**)&pK, d_Kb);
    cudaGetSymbolAddress((void**)&pV, d_Vb);
    cudaGetSymbolAddress((void**)&pG, d_Gb);
    cudaGetSymbolAddress((void**)&pO, d_O);
    cudaGetSymbolAddress((void**)&pXr, d_Xr);
    cudaGetSymbolAddress((void**)&pWqT, d_WqT);
    cudaGetSymbolAddress((void**)&pWkT, d_WkT);
    cudaGetSymbolAddress((void**)&pWvT, d_WvT);
    cudaGetSymbolAddress((void**)&pWgT, d_WgT);
    cudaGetSymbolAddress((void**)&pWoT, d_WoT);

    cudaFuncSetAttribute(gemm_tf32, cudaFuncAttributeMaxDynamicSharedMemorySize,
                         GEMM_DYNSMEM);

    // pre-passes: tf32 rounding + weight transposes
    round_x_kernel<<<(NTOK * Dn / 4) / 256, 256>>>(x, pXr);
    transpose_rt<<<dim3(KDn / 32, Dn / 32), 256>>>(Wq, pWqT, Dn, KDn);
    transpose_rt<<<dim3(KDn / 32, Dn / 32), 256>>>(Wk, pWkT, Dn, KDn);
    transpose_rt<<<dim3(VDn / 32, Dn / 32), 256>>>(Wv, pWvT, Dn, VDn);
    transpose_rt<<<dim3(VDn / 32, Dn / 32), 256>>>(Wg, pWgT, Dn, VDn);
    transpose_rt<<<dim3(Dn / 32, VDn / 32), 256>>>(Wo, pWoT, VDn, Dn);

    // projections on tensor cores (tf32 mma.sync + ldmatrix)
    gemm_tf32<<<dim3(KDn / 128, NTOK / 128), 256, GEMM_DYNSMEM>>>(pXr, pWqT, pQ, NTOK, KDn, Dn);
    gemm_tf32<<<dim3(KDn / 128, NTOK / 128), 256, GEMM_DYNSMEM>>>(pXr, pWkT, pK, NTOK, KDn, Dn);
    gemm_tf32<<<dim3(VDn / 128, NTOK / 128), 256, GEMM_DYNSMEM>>>(pXr, pWvT, pV, NTOK, VDn, Dn);
    gemm_tf32<<<dim3(VDn / 128, NTOK / 128), 256, GEMM_DYNSMEM>>>(pXr, pWgT, pG, NTOK, VDn, Dn);

    // gate path
    gemm_gk1<<<NTOK, 256>>>(x, Wgk1);
    gk_kernel<<<(NTOK * KDn) / 256, 256>>>(Wgk2, bgk);

    // chunked linear attention
    attn_chunk_kernel<<<NCB, 256>>>();
    scan_kernel<<<BH, 512>>>();
    attn_inter_kernel<<<NCB, 256>>>(norm_w);

    // output projection
    gemm_tf32<<<dim3(Dn / 128, NTOK / 128), 256, GEMM_DYNSMEM>>>(pO, pWoT, out, NTOK, Dn, Dn);
}

// round 7
// speedup vs baseline: 3.1927x; 1.3112x over previous
#include <cuda_runtime.h>
#include <cuda_fp16.h>
#include <math.h>
#include <cstdint>

// ---------------- problem constants ----------------
#define Bn 2
#define Tn 4096
#define Dn 1024
#define Hn 16
#define KDn 512
#define VDn 1024
#define HKn 32
#define HVn 64
#define CHUNKn 64
#define NC (Tn / CHUNKn)          // 64 chunks
#define NTOK (Bn * Tn)            // 8192 tokens
#define BH (Bn * Hn)              // 32
#define NCB (NC * BH)             // 2048 chunk-heads
#define SCALE_Q 0.17677669529663687f  // 1/sqrt(32)

// ---------------- scratch (static device globals; no allocation) ----------------
__device__ float d_Q[NTOK * KDn];        // 16 MB
__device__ float d_Kb[NTOK * KDn];       // 16 MB
__device__ float d_Vb[NTOK * VDn];       // 32 MB
__device__ float d_Gb[NTOK * VDn];       // 32 MB
__device__ float d_GK[NTOK * KDn];       // 16 MB
__device__ float d_t16[NTOK * 16];       // 0.5 MB
__device__ float d_M[NCB * HKn * HVn];   // 16 MB
__device__ float d_Sb[NCB * HKn * HVn];  // 16 MB
__device__ float d_dl[NCB * HKn];        // 0.25 MB
__device__ float d_O[NTOK * VDn];        // 32 MB   intra-chunk o
__device__ __half d_Xh[NTOK * Dn];       // 16 MB   x in fp16
__device__ __half d_Oh[NTOK * VDn];      // 16 MB   gated o in fp16 (Wo input)
__device__ __half d_WqT[KDn * Dn];       // 1 MB    transposed fp16 weights (K-major)
__device__ __half d_WkT[KDn * Dn];       // 1 MB
__device__ __half d_WvT[VDn * Dn];       // 2 MB
__device__ __half d_WgT[VDn * Dn];       // 2 MB
__device__ __half d_WoT[Dn * Dn];        // 2 MB

// ---------------- helpers ----------------
__device__ __forceinline__ void mma_f16(float* c, const uint32_t* a, const uint32_t* b) {
    asm volatile(
        "mma.sync.aligned.m16n8k16.row.col.f32.f16.f16.f32 "
        "{%0,%1,%2,%3}, {%4,%5,%6,%7}, {%8,%9}, {%0,%1,%2,%3};"
        : "+f"(c[0]), "+f"(c[1]), "+f"(c[2]), "+f"(c[3])
        : "r"(a[0]), "r"(a[1]), "r"(a[2]), "r"(a[3]), "r"(b[0]), "r"(b[1]));
}
__device__ __forceinline__ void ldsm_x4(uint32_t* d, uint32_t addr) {
    asm volatile("ldmatrix.sync.aligned.m8n8.x4.shared.b16 {%0,%1,%2,%3}, [%4];"
        : "=r"(d[0]), "=r"(d[1]), "=r"(d[2]), "=r"(d[3]) : "r"(addr));
}
__device__ __forceinline__ void ldsm_x2(uint32_t* d, uint32_t addr) {
    asm volatile("ldmatrix.sync.aligned.m8n8.x2.shared.b16 {%0,%1}, [%2];"
        : "=r"(d[0]), "=r"(d[1]) : "r"(addr));
}

// ---------------- fp16 tensor-core GEMM: C[M,N] = A[M,K] * BT[N,K]^T ----------------
// Operands fp16 K-major, fp32 accumulate. Tile 128x128, K-step 64 (128B rows),
// 3-stage cp.async pipeline (96KB smem -> 2 CTAs/SM), SW128 xor swizzle,
// ldmatrix fragment loads, mma.sync m16n8k16.
#define GST 3
#define STAGE_BYTES 32768   // A 16KB + B 16KB
#define GEMM_DYNSMEM (GST * STAGE_BYTES)

__global__ __launch_bounds__(256, 2) void gemm_f16(
    const __half* __restrict__ A, const __half* __restrict__ BT,
    float* __restrict__ C, int M, int N, int K)
{
    extern __shared__ __align__(16) char dyn[];
    uint32_t sbase;
    asm("{ .reg .u64 t; cvta.to.shared.u64 t, %1; cvt.u32.u64 %0, t; }"
        : "=r"(sbase) : "l"(dyn));
    const int t = threadIdx.x;
    const int lane = t & 31;
    const int wrow = (t >> 5) >> 2;   // 0..1  (64 rows each)
    const int wcol = (t >> 5) & 3;    // 0..3  (32 cols each)
    const int bm = blockIdx.y << 7, bn = blockIdx.x << 7;
    const int NT = K >> 6;            // K tiles of 64 halves

    // ldmatrix lane addresses (byte offsets in a 128-row x 64-half tile, 128B/row).
    // A x4 matrices: (r,+0B),(r+8,+0B),(r,+16B),(r+8,+16B) -> fp16 A frag {a0..a3}
    // B x2 matrices: (n,+0B),(n,+16B) -> fp16 B frag {b0,b1}
    const int aoff = (wrow * 64 + ((lane >> 3) & 1) * 8 + (lane & 7)) * 128
                   + ((lane >> 4) & 1) * 16;              // + mt*2048 + ks*32
    const int boff = (wcol * 32 + (lane & 7)) * 128
                   + ((lane >> 3) & 1) * 16;              // + nt*1024 + ks*32

    #define LOAD_TILE(kt)                                                              \
    do {                                                                               \
        const int k0_ = (kt) << 6;                                                     \
        const uint32_t stg_ = sbase + ((kt) % GST) * STAGE_BYTES;                      \
        _Pragma("unroll")                                                              \
        for (int i_ = 0; i_ < 4; i_++) {                                               \
            int q_ = t + (i_ << 8);                                                    \
            int row_ = q_ >> 3, c16_ = q_ & 7;                                         \
            const __half* g_ = A + (size_t)(bm + row_) * K + k0_ + (c16_ << 3);        \
            uint32_t off_ = (uint32_t)((row_ << 7) + (c16_ << 4));                     \
            uint32_t dst_ = stg_ + (off_ ^ ((off_ >> 3) & 0x70));                      \
            asm volatile("cp.async.cg.shared.global [%0], [%1], 16;" :: "r"(dst_), "l"(g_)); \
        }                                                                              \
        _Pragma("unroll")                                                              \
        for (int i_ = 4; i_ < 8; i_++) {                                               \
            int q_ = t + (i_ << 8) - 1024;                                             \
            int row_ = q_ >> 3, c16_ = q_ & 7;                                         \
            const __half* g_ = BT + (size_t)(bn + row_) * K + k0_ + (c16_ << 3);       \
            uint32_t off_ = (uint32_t)((row_ << 7) + (c16_ << 4));                     \
            uint32_t dst_ = stg_ + 16384 + (off_ ^ ((off_ >> 3) & 0x70));              \
            asm volatile("cp.async.cg.shared.global [%0], [%1], 16;" :: "r"(dst_), "l"(g_)); \
        }                                                                              \
        asm volatile("cp.async.commit_group;");                                        \
    } while (0)

    float acc[4][4][4];
    #pragma unroll
    for (int i = 0; i < 4; i++)
        #pragma unroll
        for (int j = 0; j < 4; j++)
            #pragma unroll
            for (int e = 0; e < 4; e++) acc[i][j][e] = 0.f;

    // prologue: 2 tiles in flight
    LOAD_TILE(0);
    LOAD_TILE(1);

    for (int kt = 0; kt < NT; kt++) {
        asm volatile("cp.async.wait_group %0;" :: "n"(GST - 2));   // tile kt resident
        __syncthreads();
        const int nt_ = kt + GST - 1;
        if (nt_ < NT) LOAD_TILE(nt_);   // overwrites buffer consumed at iter kt-1

        const uint32_t sAb = sbase + (kt % GST) * STAGE_BYTES;
        const uint32_t sBb = sAb + 16384;

        #pragma unroll
        for (int ks = 0; ks < 4; ks++) {     // 4 x K=16 per 64-half tile
            uint32_t af[4][4], bf[4][2];
            #pragma unroll
            for (int mt = 0; mt < 4; mt++) {
                int o = aoff + mt * 2048 + ks * 32;
                ldsm_x4(af[mt], sAb + (o ^ ((o >> 3) & 0x70)));
            }
            #pragma unroll
            for (int nt = 0; nt < 4; nt++) {
                int o = boff + nt * 1024 + ks * 32;
                ldsm_x2(bf[nt], sBb + (o ^ ((o >> 3) & 0x70)));
            }
            #pragma unroll
            for (int mt = 0; mt < 4; mt++)
                #pragma unroll
                for (int nt = 0; nt < 4; nt++)
                    mma_f16(acc[mt][nt], af[mt], bf[nt]);
        }
    }

    // epilogue: direct register -> global stores (float2 per c-pair)
    #pragma unroll
    for (int mt = 0; mt < 4; mt++) {
        #pragma unroll
        for (int nt = 0; nt < 4; nt++) {
            int r0 = bm + wrow * 64 + mt * 16 + (lane >> 2);
            int c0 = bn + wcol * 32 + nt * 8 + (lane & 3) * 2;
            float2 v0 = make_float2(acc[mt][nt][0], acc[mt][nt][1]);
            float2 v1 = make_float2(acc[mt][nt][2], acc[mt][nt][3]);
            *(float2*)&C[(size_t)r0 * N + c0] = v0;
            *(float2*)&C[(size_t)(r0 + 8) * N + c0] = v1;
        }
    }
}

// ---------------- pre-passes: fp16 conversion + weight transpose ----------------
__global__ __launch_bounds__(256) void conv_x_kernel(const float* __restrict__ X,
                                                     __half* __restrict__ Y)
{
    int i = blockIdx.x * 256 + threadIdx.x;   // over float4s
    float4 v = ((const float4*)X)[i];
    __half2 lo = __floats2half2_rn(v.x, v.y);
    __half2 hi = __floats2half2_rn(v.z, v.w);
    ((uint2*)Y)[i] = make_uint2(*(uint32_t*)&lo, *(uint32_t*)&hi);
}

__global__ __launch_bounds__(256) void transpose_h(const float* __restrict__ W,
                                                   __half* __restrict__ WT,
                                                   int Kd, int Nd)
{
    __shared__ float tl[32][33];
    int n0 = blockIdx.x * 32, k0 = blockIdx.y * 32;
    int tx = threadIdx.x & 31, ty = threadIdx.x >> 5;   // 32x8
    #pragma unroll
    for (int r = 0; r < 32; r += 8)
        tl[ty + r][tx] = W[(size_t)(k0 + ty + r) * Nd + n0 + tx];
    __syncthreads();
    #pragma unroll
    for (int r = 0; r < 32; r += 8)
        WT[(size_t)(n0 + ty + r) * Kd + k0 + tx] = __float2half_rn(tl[tx][ty + r]);
}

// ---------------- gk low-rank stage 1: t16 = x @ Wgk1 (fp32) ----------
__global__ __launch_bounds__(256) void gemm_gk1(const float* __restrict__ X,
                                                const float* __restrict__ W)
{
    __shared__ float red[256];
    const int m = blockIdx.x;
    const int tx = threadIdx.x & 15;
    const int ty = threadIdx.x >> 4;
    float acc = 0.f;
    const float* xr = X + (size_t)m * Dn;
    for (int k = ty; k < Dn; k += 16)
        acc += xr[k] * W[k * 16 + tx];
    red[threadIdx.x] = acc;
    __syncthreads();
    for (int s = 8; s > 0; s >>= 1) {
        if (ty < s) red[ty * 16 + tx] += red[(ty + s) * 16 + tx];
        __syncthreads();
    }
    if (ty == 0) d_t16[m * 16 + tx] = red[tx];
}

// ---------------- gk stage 2 ----------------
__global__ __launch_bounds__(256) void gk_kernel(const float* __restrict__ W2,
                                                 const float* __restrict__ bgk)
{
    int idx = blockIdx.x * blockDim.x + threadIdx.x;
    int m = idx >> 9;
    int n = idx & 511;
    const float* t = d_t16 + m * 16;
    float z = bgk[n];
    #pragma unroll
    for (int k = 0; k < 16; k++) z += t[k] * W2[k * KDn + n];
    float ls = fminf(z, 0.f) - log1pf(expf(-fabsf(z)));
    d_GK[idx] = ls * (1.f / 16.f);
}

// ---------------- attention phase A ----------------
__global__ __launch_bounds__(256) void attn_chunk_kernel()
{
    __shared__ float s_qe[2048];
    __shared__ float s_kd[2048];
    __shared__ float s_v[4096];
    __shared__ float s_A[2048];
    __shared__ float s_bl[32], s_dl[32];

    const int cb = blockIdx.x;
    const int bh = cb & 31, c = cb >> 5;
    const int b = bh >> 4, h = bh & 15;
    const int t = threadIdx.x;
    const size_t tok0 = (size_t)b * Tn + (size_t)c * CHUNKn;

    for (int e = t; e < 2048; e += 256) {
        int i = e >> 5, k = e & 31;
        s_qe[e] = d_GK[(tok0 + i) * KDn + h * HKn + k];
    }
    __syncthreads();
    if (t < 32) {
        float run = 0.f;
        for (int i = 0; i < 64; i++) { run += s_qe[i * 32 + t]; s_qe[i * 32 + t] = run; }
        s_bl[t] = run;
        s_dl[t] = expf(run);
    }
    __syncthreads();
    for (int e = t; e < 2048; e += 256) {
        int i = e >> 5, k = e & 31;
        float bb = s_qe[e];
        float kv = d_Kb[(tok0 + i) * KDn + h * HKn + k];
        s_kd[i * 32 + ((k ^ i) & 31)] = kv * expf(-bb);
        float qv = d_Q[(tok0 + i) * KDn + h * HKn + k];
        s_qe[e] = qv * expf(bb) * SCALE_Q;
    }
    for (int e = t; e < 4096; e += 256) {
        int i = e >> 6, v = e & 63;
        s_v[e] = d_Vb[(tok0 + i) * VDn + h * HVn + v];
    }
    __syncthreads();
    for (int o = t; o < 2048; o += 256) {
        int k = o >> 6, v = o & 63;
        float acc = 0.f;
        #pragma unroll 8
        for (int j = 0; j < 64; j++)
            acc += s_kd[j * 32 + ((k ^ j) & 31)] * s_v[j * 64 + v];
        d_M[(size_t)cb * 2048 + o] = acc * s_dl[k];
    }
    if (t < 32) d_dl[cb * 32 + t] = s_dl[t];

    #pragma unroll
    for (int half = 0; half < 2; half++) {
        __syncthreads();
        for (int o = t; o < 2048; o += 256) {
            int il = o >> 6, j = o & 63;
            int i = half * 32 + il;
            float acc = 0.f;
            if (j <= i) {
                #pragma unroll
                for (int k = 0; k < 32; k++)
                    acc += s_qe[i * 32 + k] * s_kd[j * 32 + ((k ^ j) & 31)];
            }
            s_A[o] = acc;
        }
        __syncthreads();
        for (int o = t; o < 2048; o += 256) {
            int il = o >> 6, v = o & 63;
            int i = half * 32 + il;
            float acc = 0.f;
            #pragma unroll 8
            for (int j = 0; j < 64; j++)
                acc += s_A[il * 64 + j] * s_v[j * 64 + v];
            d_O[(tok0 + i) * VDn + h * HVn + v] = acc;
        }
    }
}

// ---------------- attention phase B: serial state scan ----------------
__global__ __launch_bounds__(512) void scan_kernel()
{
    const int bh = blockIdx.x;
    const int t = threadIdx.x;
    float S[4] = {0.f, 0.f, 0.f, 0.f};
    for (int c = 0; c < NC; c++) {
        const int ch = c * 32 + bh;
        const size_t base = (size_t)ch * 2048;
        #pragma unroll
        for (int e = 0; e < 4; e++) {
            int idx = e * 512 + t;
            d_Sb[base + idx] = S[e];
            float dl = d_dl[ch * 32 + (idx >> 6)];
            S[e] = dl * S[e] + d_M[base + idx];
        }
    }
}

// ---------------- attention phase C: inter-chunk + RMSNorm + SiLU gate ------------
// Final gated value stored as fp16 (feeds the Wo fp16 GEMM).
__global__ __launch_bounds__(256) void attn_inter_kernel(const float* __restrict__ norm_w)
{
    __shared__ float s_qe[2048];
    __shared__ float s_S[2048];
    __shared__ float red[8];

    const int cb = blockIdx.x;
    const int bh = cb & 31, c = cb >> 5;
    const int b = bh >> 4, h = bh & 15;
    const int t = threadIdx.x;
    const size_t tok0 = (size_t)b * Tn + (size_t)c * CHUNKn;

    for (int e = t; e < 2048; e += 256)
        s_qe[e] = d_GK[(tok0 + (e >> 5)) * KDn + h * HKn + (e & 31)];
    for (int e = t; e < 2048; e += 256)
        s_S[e] = d_Sb[(size_t)cb * 2048 + e];
    __syncthreads();
    if (t < 32) {
        float run = 0.f;
        for (int i = 0; i < 64; i++) { run += s_qe[i * 32 + t]; s_qe[i * 32 + t] = run; }
    }
    __syncthreads();
    for (int e = t; e < 2048; e += 256) {
        float bb = s_qe[e];
        float qv = d_Q[(tok0 + (e >> 5)) * KDn + h * HKn + (e & 31)];
        s_qe[e] = qv * expf(bb) * SCALE_Q;
    }
    __syncthreads();

    const int wid = t >> 5;
    for (int r = 0; r < 16; r++) {
        int o = t + 256 * r;
        int i = o >> 6, v = o & 63;
        size_t gi = (tok0 + i) * VDn + h * HVn + v;
        float acc = d_O[gi];
        #pragma unroll
        for (int k = 0; k < 32; k++)
            acc += s_qe[i * 32 + k] * s_S[k * 64 + v];
        float ss = acc * acc;
        #pragma unroll
        for (int off = 16; off > 0; off >>= 1)
            ss += __shfl_xor_sync(0xffffffffu, ss, off);
        if ((t & 31) == 0) red[wid] = ss;
        __syncthreads();
        float rowss = red[(t >> 6) * 2] + red[(t >> 6) * 2 + 1];
        __syncthreads();
        float rinv = rsqrtf(rowss * (1.f / 64.f) + 1e-5f);
        float g = d_Gb[gi];
        float sg = 1.f / (1.f + expf(-g));
        d_Oh[gi] = __float2half_rn(acc * rinv * norm_w[v] * (g * sg));
    }
}

// ---------------- launch ----------------
extern "C" void kernel_launch(void* const* d_in, const int* in_sizes, int n_in,
                              void* d_out, int out_size)
{
    const float* x      = (const float*)d_in[0];
    const float* Wq     = (const float*)d_in[1];
    const float* Wk     = (const float*)d_in[2];
    const float* Wv     = (const float*)d_in[3];
    const float* Wgk1   = (const float*)d_in[4];
    const float* Wgk2   = (const float*)d_in[5];
    const float* bgk    = (const float*)d_in[6];
    const float* Wg     = (const float*)d_in[7];
    const float* norm_w = (const float*)d_in[8];
    const float* Wo     = (const float*)d_in[9];
    float* out = (float*)d_out;

    float *pQ, *pK, *pV, *pG, *pO;
    __half *pXh, *pOh, *pWqT, *pWkT, *pWvT, *pWgT, *pWoT;
    cudaGetSymbolAddress((void**)&pQ, d_Q);
    cudaGetSymbolAddress((void**)&pK, d_Kb);
    cudaGetSymbolAddress((void**)&pV, d_Vb);
    cudaGetSymbolAddress((void**)&pG, d_Gb);
    cudaGetSymbolAddress((void**)&pO, d_O);
    cudaGetSymbolAddress((void**)&pXh, d_Xh);
    cudaGetSymbolAddress((void**)&pOh, d_Oh);
    cudaGetSymbolAddress((void**)&pWqT, d_WqT);
    cudaGetSymbolAddress((void**)&pWkT, d_WkT);
    cudaGetSymbolAddress((void**)&pWvT, d_WvT);
    cudaGetSymbolAddress((void**)&pWgT, d_WgT);
    cudaGetSymbolAddress((void**)&pWoT, d_WoT);

    cudaFuncSetAttribute(gemm_f16, cudaFuncAttributeMaxDynamicSharedMemorySize,
                         GEMM_DYNSMEM);

    // pre-passes: fp16 conversion + weight transposes
    conv_x_kernel<<<(NTOK * Dn / 4) / 256, 256>>>(x, pXh);
    transpose_h<<<dim3(KDn / 32, Dn / 32), 256>>>(Wq, pWqT, Dn, KDn);
    transpose_h<<<dim3(KDn / 32, Dn / 32), 256>>>(Wk, pWkT, Dn, KDn);
    transpose_h<<<dim3(VDn / 32, Dn / 32), 256>>>(Wv, pWvT, Dn, VDn);
    transpose_h<<<dim3(VDn / 32, Dn / 32), 256>>>(Wg, pWgT, Dn, VDn);
    transpose_h<<<dim3(Dn / 32, VDn / 32), 256>>>(Wo, pWoT, VDn, Dn);

    // projections on tensor cores (fp16 mma.sync m16n8k16 + ldmatrix)
    gemm_f16<<<dim3(KDn / 128, NTOK / 128), 256, GEMM_DYNSMEM>>>(pXh, pWqT, pQ, NTOK, KDn, Dn);
    gemm_f16<<<dim3(KDn / 128, NTOK / 128), 256, GEMM_DYNSMEM>>>(pXh, pWkT, pK, NTOK, KDn, Dn);
    gemm_f16<<<dim3(VDn / 128, NTOK / 128), 256, GEMM_DYNSMEM>>>(pXh, pWvT, pV, NTOK, VDn, Dn);
    gemm_f16<<<dim3(VDn / 128, NTOK / 128), 256, GEMM_DYNSMEM>>>(pXh, pWgT, pG, NTOK, VDn, Dn);

    // gate path (fp32 throughout)
    gemm_gk1<<<NTOK, 256>>>(x, Wgk1);
    gk_kernel<<<(NTOK * KDn) / 256, 256>>>(Wgk2, bgk);

    // chunked linear attention
    attn_chunk_kernel<<<NCB, 256>>>();
    scan_kernel<<<BH, 512>>>();
    attn_inter_kernel<<<NCB, 256>>>(norm_w);

    // output projection
    gemm_f16<<<dim3(Dn / 128, NTOK / 128), 256, GEMM_DYNSMEM>>>(pOh, pWoT, out, NTOK, Dn, Dn);
}